// round 12
// baseline (speedup 1.0000x reference)
#include <cuda_runtime.h>
#include <cuda_bf16.h>
#include <cstdint>

#define NB 128
#define CD 256
#define KK 64
#define PT 1024

// ---- smem byte offsets (per-CTA, 2 CTAs/SM) ----
#define SM_X    0            // x tile bf16 [256 c][256 B] XOR-swizzled (no pad)
#define SM_W    65536        // W bf16 [64 k][512 B] swizzled
#define SM_AT   98304        // at bf16 [64 k][256 B] swizzled; SQ [128][9]f aliases here
#define SM_ASUM 114688       // 64 f
#define SM_BIAS 114944       // 64 f
#define SM_FLAG 115200       // 1 u32
#define SM_TOTAL 115216
// epilogue aliases (X dead): RED [64][5]f @ SM_X, RK [64]f @ SM_X+2048, G2 @ SM_X+2560

// cross-CTA merge scratch
__device__ float    g_agg2[2 * NB][KK * CD];   // 16 MB partial aggs
__device__ float    g_asum2[2 * NB][KK];
__device__ unsigned g_cnt[NB];

__device__ __forceinline__ uint32_t smem_u32(const void* p) {
    uint32_t a;
    asm("{ .reg .u64 t; cvta.to.shared.u64 t, %1; cvt.u32.u64 %0, t; }" : "=r"(a) : "l"(p));
    return a;
}
__device__ __forceinline__ uint32_t bf2(float lo, float hi) {
    uint32_t r;
    asm("cvt.rn.bf16x2.f32 %0, %1, %2;" : "=r"(r) : "f"(hi), "f"(lo));
    return r;
}
__device__ __forceinline__ void ldm4t(uint32_t* r, uint32_t addr) {
    asm volatile("ldmatrix.sync.aligned.m8n8.x4.trans.shared.b16 {%0,%1,%2,%3}, [%4];"
                 : "=r"(r[0]), "=r"(r[1]), "=r"(r[2]), "=r"(r[3]) : "r"(addr));
}
__device__ __forceinline__ void ldm4(uint32_t* r, uint32_t addr) {
    asm volatile("ldmatrix.sync.aligned.m8n8.x4.shared.b16 {%0,%1,%2,%3}, [%4];"
                 : "=r"(r[0]), "=r"(r[1]), "=r"(r[2]), "=r"(r[3]) : "r"(addr));
}
__device__ __forceinline__ void mma_bf16(float* d, const uint32_t* a, uint32_t b0, uint32_t b1) {
    asm volatile("mma.sync.aligned.m16n8k16.row.col.f32.bf16.bf16.f32 "
                 "{%0,%1,%2,%3}, {%4,%5,%6,%7}, {%8,%9}, {%0,%1,%2,%3};"
                 : "+f"(d[0]), "+f"(d[1]), "+f"(d[2]), "+f"(d[3])
                 : "r"(a[0]), "r"(a[1]), "r"(a[2]), "r"(a[3]), "r"(b0), "r"(b1));
}
__device__ __forceinline__ void sts16(uint32_t addr, __nv_bfloat16 v) {
    unsigned short u = *(unsigned short*)&v;
    asm volatile("st.shared.u16 [%0], %1;" :: "r"(addr), "h"(u) : "memory");
}

__global__ __launch_bounds__(256, 2) void netvlad_mma(
    const float* __restrict__ x, const float* __restrict__ w,
    const float* __restrict__ b, const float* __restrict__ cent,
    float* __restrict__ out) {
    extern __shared__ char smem[];
    float* smf = (float*)smem;
    const uint32_t sb = smem_u32(smem);
    const int t = threadIdx.x, lane = t & 31, wp = t >> 5;     // 8 warps
    const int la = lane & 7, grp = lane >> 3, qr = lane >> 2, qc = lane & 3;
    const int kg = wp & 1, cg = wp >> 1;                       // GEMM2 k32 x c64
    const int bid = blockIdx.x, n = bid >> 1, h = bid & 1;
    const float* xn = x + (size_t)n * CD * PT;

    // ---- one-time: W -> swizzled bf16 smem; bias; asum=0 ----
#pragma unroll
    for (int i = 0; i < 32; i++) {
        int id2 = t + (i << 8);
        int kk = id2 >> 7, c2 = id2 & 127;
        float2 v = ((const float2*)w)[id2];
        *(uint32_t*)(smem + SM_W + kk * 512 + (((uint32_t)(c2 * 4)) ^ ((kk & 7) << 4))) =
            bf2(v.x, v.y);
    }
    if (t < KK) { smf[(SM_ASUM >> 2) + t] = 0.f; smf[(SM_BIAS >> 2) + t] = b[t]; }

    const uint32_t aG1off = (uint32_t)(la + ((grp >> 1) << 3)) * 256 +
        ((uint32_t)((wp * 16 + ((grp & 1) << 3)) * 2) ^ ((uint32_t)la << 4));
    const int plo = wp * 16 + qr, phi = plo + 8;
    const int pq = t & 31, cb = t >> 5;
    const uint32_t xsw = ((uint32_t)(pq * 8)) ^ ((uint32_t)cb << 4);

    float agg[2][8][4];
#pragma unroll
    for (int i = 0; i < 2; i++)
#pragma unroll
        for (int j = 0; j < 8; j++)
#pragma unroll
            for (int q = 0; q < 4; q++) agg[i][j][q] = 0.f;

    for (int tl = 0; tl < 4; tl++) {
        const int p0 = h * 512 + tl * 128;

        // ---- phase A: x -> swizzled bf16 X + SQ partials (SQ aliased in AT) ----
        {
            const float* xp = xn + p0 + pq * 4;
            float s0 = 0.f, s1 = 0.f, s2 = 0.f, s3 = 0.f;
#pragma unroll 8
            for (int i = 0; i < 32; i++) {
                int c = cb + (i << 3);
                float4 v = *(const float4*)(xp + (size_t)c * PT);
                s0 += v.x * v.x; s1 += v.y * v.y; s2 += v.z * v.z; s3 += v.w * v.w;
                *(uint2*)(smem + SM_X + c * 256 + xsw) =
                    make_uint2(bf2(v.x, v.y), bf2(v.z, v.w));
            }
            float* sq = smf + (SM_AT >> 2);
            sq[(pq * 4 + 0) * 9 + cb] = s0;
            sq[(pq * 4 + 1) * 9 + cb] = s1;
            sq[(pq * 4 + 2) * 9 + cb] = s2;
            sq[(pq * 4 + 3) * 9 + cb] = s3;
        }
        __syncthreads();   // S1

        // ---- read SQ (before AT overwrites it), then barrier ----
        float qlo = 0.f, qhi = 0.f;
        {
            const float* sqp = smf + (SM_AT >> 2);
#pragma unroll
            for (int i = 0; i < 8; i++) {
                qlo += sqp[plo * 9 + i];
                qhi += sqp[phi * 9 + i];
            }
        }
        __syncthreads();   // S2 (SQ consumed; AT writes now safe)
        const float invlo = 1.0f / fmaxf(sqrtf(qlo), 1e-12f);
        const float invhi = 1.0f / fmaxf(sqrtf(qhi), 1e-12f);

        // ---- GEMM1: logits[p][k] (all 8 warps, 16p each, full k64) ----
        float acc[8][4];
#pragma unroll
        for (int i = 0; i < 8; i++)
#pragma unroll
            for (int q = 0; q < 4; q++) acc[i][q] = 0.f;
#pragma unroll
        for (int cb32 = 0; cb32 < 256; cb32 += 32) {
            uint32_t afA[4], afB[4];
            ldm4t(afA, sb + SM_X + aG1off + (uint32_t)cb32 * 256);
            ldm4t(afB, sb + SM_X + aG1off + (uint32_t)(cb32 + 16) * 256);
#pragma unroll
            for (int nt = 0; nt < 8; nt++) {
                uint32_t wf[4];
                ldm4(wf, sb + SM_W + (uint32_t)(nt * 8 + la) * 512 +
                         (((uint32_t)(grp * 16 + cb32 * 2)) ^ ((uint32_t)la << 4)));
                mma_bf16(acc[nt], afA, wf[0], wf[1]);
                mma_bf16(acc[nt], afB, wf[2], wf[3]);
            }
        }

        // ---- warp-local softmax ----
        float mlo = -1e30f, mhi = -1e30f;
#pragma unroll
        for (int nt = 0; nt < 8; nt++) {
            float b0 = smf[(SM_BIAS >> 2) + nt * 8 + qc * 2];
            float b1 = smf[(SM_BIAS >> 2) + nt * 8 + qc * 2 + 1];
            acc[nt][0] = acc[nt][0] * invlo + b0;
            acc[nt][1] = acc[nt][1] * invlo + b1;
            acc[nt][2] = acc[nt][2] * invhi + b0;
            acc[nt][3] = acc[nt][3] * invhi + b1;
            mlo = fmaxf(mlo, fmaxf(acc[nt][0], acc[nt][1]));
            mhi = fmaxf(mhi, fmaxf(acc[nt][2], acc[nt][3]));
        }
        mlo = fmaxf(mlo, __shfl_xor_sync(0xffffffffu, mlo, 1));
        mlo = fmaxf(mlo, __shfl_xor_sync(0xffffffffu, mlo, 2));
        mhi = fmaxf(mhi, __shfl_xor_sync(0xffffffffu, mhi, 1));
        mhi = fmaxf(mhi, __shfl_xor_sync(0xffffffffu, mhi, 2));
        float slo = 0.f, shi = 0.f;
#pragma unroll
        for (int nt = 0; nt < 8; nt++) {
            acc[nt][0] = __expf(acc[nt][0] - mlo); slo += acc[nt][0];
            acc[nt][1] = __expf(acc[nt][1] - mlo); slo += acc[nt][1];
            acc[nt][2] = __expf(acc[nt][2] - mhi); shi += acc[nt][2];
            acc[nt][3] = __expf(acc[nt][3] - mhi); shi += acc[nt][3];
        }
        slo += __shfl_xor_sync(0xffffffffu, slo, 1);
        slo += __shfl_xor_sync(0xffffffffu, slo, 2);
        shi += __shfl_xor_sync(0xffffffffu, shi, 1);
        shi += __shfl_xor_sync(0xffffffffu, shi, 2);
        const float rlo = 1.0f / slo, rhi = 1.0f / shi;
        const float wlo = rlo * invlo, whi = rhi * invhi;

        // ---- at writes (swizzled) + asum via smem float atomics ----
        {
            const uint32_t swl0 = ((uint32_t)(plo * 2)) ^ ((uint32_t)(qc * 2) << 4);
            const uint32_t swl1 = ((uint32_t)(plo * 2)) ^ ((uint32_t)(qc * 2 + 1) << 4);
            const uint32_t swh0 = ((uint32_t)(phi * 2)) ^ ((uint32_t)(qc * 2) << 4);
            const uint32_t swh1 = ((uint32_t)(phi * 2)) ^ ((uint32_t)(qc * 2 + 1) << 4);
            float asv[16];
#pragma unroll
            for (int nt = 0; nt < 8; nt++) {
                asv[nt * 2]     = acc[nt][0] * rlo + acc[nt][2] * rhi;
                asv[nt * 2 + 1] = acc[nt][1] * rlo + acc[nt][3] * rhi;
                uint32_t base0 = sb + SM_AT + (uint32_t)(nt * 8 + qc * 2) * 256;
                sts16(base0 + swl0, __float2bfloat16(acc[nt][0] * wlo));
                sts16(base0 + 256 + swl1, __float2bfloat16(acc[nt][1] * wlo));
                sts16(base0 + swh0, __float2bfloat16(acc[nt][2] * whi));
                sts16(base0 + 256 + swh1, __float2bfloat16(acc[nt][3] * whi));
            }
#pragma unroll
            for (int j = 0; j < 16; j++) {
                asv[j] += __shfl_xor_sync(0xffffffffu, asv[j], 4);
                asv[j] += __shfl_xor_sync(0xffffffffu, asv[j], 8);
                asv[j] += __shfl_xor_sync(0xffffffffu, asv[j], 16);
            }
            if (lane < 4) {
#pragma unroll
                for (int nt = 0; nt < 8; nt++) {
                    atomicAdd(&smf[(SM_ASUM >> 2) + nt * 8 + lane * 2], asv[nt * 2]);
                    atomicAdd(&smf[(SM_ASUM >> 2) + nt * 8 + lane * 2 + 1], asv[nt * 2 + 1]);
                }
            }
        }
        __syncthreads();   // S3

        // ---- GEMM2: agg[k32][c64] += at @ x^T (all 8 warps) ----
#pragma unroll
        for (int q4 = 0; q4 < 4; q4++) {
            uint32_t afr[2][2][4];
#pragma unroll
            for (int mt = 0; mt < 2; mt++) {
                uint32_t krow = (uint32_t)(kg * 32 + mt * 16 + la + ((grp & 1) << 3));
                uint32_t colA = (uint32_t)(((grp >> 1) << 4) + q4 * 64);
                ldm4(afr[mt][0], sb + SM_AT + krow * 256 + (colA ^ ((uint32_t)la << 4)));
                ldm4(afr[mt][1], sb + SM_AT + krow * 256 + ((colA + 32) ^ ((uint32_t)la << 4)));
            }
#pragma unroll
            for (int ntp = 0; ntp < 2; ntp++) {
                uint32_t bfr[4][4];
#pragma unroll
                for (int j = 0; j < 4; j++) {
                    uint32_t crow = (uint32_t)(cg * 64 + (ntp * 4 + j) * 8 + la);
                    uint32_t colB = (uint32_t)((grp << 4) + q4 * 64);
                    ldm4(bfr[j], sb + SM_X + crow * 256 + (colB ^ ((uint32_t)la << 4)));
                }
#pragma unroll
                for (int mt = 0; mt < 2; mt++)
#pragma unroll
                    for (int j = 0; j < 4; j++) {
                        mma_bf16(agg[mt][ntp * 4 + j], afr[mt][0], bfr[j][0], bfr[j][1]);
                        mma_bf16(agg[mt][ntp * 4 + j], afr[mt][1], bfr[j][2], bfr[j][3]);
                    }
            }
        }
        __syncthreads();   // S4
    }

    // ---- cross-CTA merge: both write partials; second finisher merges ----
    float* af = &agg[0][0][0];
    {
        float* gp = g_agg2[bid];
#pragma unroll
        for (int j = 0; j < 16; j++)
            *(float4*)(gp + j * 1024 + t * 4) =
                make_float4(af[j * 4], af[j * 4 + 1], af[j * 4 + 2], af[j * 4 + 3]);
        if (t < KK) g_asum2[bid][t] = smf[(SM_ASUM >> 2) + t];
    }
    __threadfence();
    __syncthreads();
    if (t == 0) {
        unsigned r = atomicAdd(&g_cnt[n], 1u);
        if (r == 1u) g_cnt[n] = 0u;        // reset for next replay
        *(unsigned*)(smem + SM_FLAG) = r;
    }
    __syncthreads();
    if (*(unsigned*)(smem + SM_FLAG) == 0u) return;   // first finisher exits
    __threadfence();
    {
        const float* gp = g_agg2[bid ^ 1];
#pragma unroll
        for (int j = 0; j < 16; j++) {
            float4 v = *(const float4*)(gp + j * 1024 + t * 4);
            af[j * 4] += v.x; af[j * 4 + 1] += v.y;
            af[j * 4 + 2] += v.z; af[j * 4 + 3] += v.w;
        }
        if (t < KK) smf[(SM_ASUM >> 2) + t] += g_asum2[bid ^ 1][t];
    }
    __syncthreads();

    // ---- epilogue (loser CTA only): vlad, intra-norm, global norm, store ----
#pragma unroll
    for (int mt = 0; mt < 2; mt++) {
        int kA = kg * 32 + mt * 16 + qr, kB = kA + 8;
        float as0 = smf[(SM_ASUM >> 2) + kA];
        float as1 = smf[(SM_ASUM >> 2) + kB];
#pragma unroll
        for (int nt = 0; nt < 8; nt++) {
            int c0 = cg * 64 + nt * 8 + qc * 2;
            float2 ce0 = *(const float2*)(cent + kA * CD + c0);
            float2 ce1 = *(const float2*)(cent + kB * CD + c0);
            agg[mt][nt][0] -= as0 * ce0.x;
            agg[mt][nt][1] -= as0 * ce0.y;
            agg[mt][nt][2] -= as1 * ce1.x;
            agg[mt][nt][3] -= as1 * ce1.y;
        }
    }
#pragma unroll
    for (int mt = 0; mt < 2; mt++) {
        float sA = 0.f, sB = 0.f;
#pragma unroll
        for (int nt = 0; nt < 8; nt++) {
            sA += agg[mt][nt][0] * agg[mt][nt][0] + agg[mt][nt][1] * agg[mt][nt][1];
            sB += agg[mt][nt][2] * agg[mt][nt][2] + agg[mt][nt][3] * agg[mt][nt][3];
        }
        sA += __shfl_xor_sync(0xffffffffu, sA, 1);
        sA += __shfl_xor_sync(0xffffffffu, sA, 2);
        sB += __shfl_xor_sync(0xffffffffu, sB, 1);
        sB += __shfl_xor_sync(0xffffffffu, sB, 2);
        if (qc == 0) {
            int kA = kg * 32 + mt * 16 + qr;
            smf[(SM_X >> 2) + kA * 5 + cg] = sA;
            smf[(SM_X >> 2) + (kA + 8) * 5 + cg] = sB;
        }
    }
    __syncthreads();
    if (t < 64) {
        float ss = 0.f;
#pragma unroll
        for (int i = 0; i < 4; i++) ss += smf[(SM_X >> 2) + t * 5 + i];
        float dk = fmaxf(sqrtf(ss), 1e-12f);
        smf[(SM_X >> 2) + 512 + t] = 1.0f / dk;   // RK @ SM_X+2048
        float gp = ss / (dk * dk);
        gp += __shfl_xor_sync(0xffffffffu, gp, 16);
        gp += __shfl_xor_sync(0xffffffffu, gp, 8);
        gp += __shfl_xor_sync(0xffffffffu, gp, 4);
        gp += __shfl_xor_sync(0xffffffffu, gp, 2);
        gp += __shfl_xor_sync(0xffffffffu, gp, 1);
        if (lane == 0) smf[(SM_X >> 2) + 640 + wp] = gp;   // G2 @ SM_X+2560
    }
    __syncthreads();
    const float rg = 1.0f / fmaxf(sqrtf(smf[(SM_X >> 2) + 640] + smf[(SM_X >> 2) + 641]), 1e-12f);
    float* on = out + (size_t)n * KK * CD;
#pragma unroll
    for (int mt = 0; mt < 2; mt++) {
        int kA = kg * 32 + mt * 16 + qr, kB = kA + 8;
        float r0 = smf[(SM_X >> 2) + 512 + kA] * rg;
        float r1 = smf[(SM_X >> 2) + 512 + kB] * rg;
#pragma unroll
        for (int nt = 0; nt < 8; nt++) {
            int c0 = cg * 64 + nt * 8 + qc * 2;
            *(float2*)(on + kA * CD + c0) =
                make_float2(agg[mt][nt][0] * r0, agg[mt][nt][1] * r0);
            *(float2*)(on + kB * CD + c0) =
                make_float2(agg[mt][nt][2] * r1, agg[mt][nt][3] * r1);
        }
    }
}

// ------------------------------------------------------------------------------
extern "C" void kernel_launch(void* const* d_in, const int* in_sizes, int n_in,
                              void* d_out, int out_size) {
    const float* x    = (const float*)d_in[0];  // (128, 256, 32, 32)
    const float* w    = (const float*)d_in[1];  // (64, 256)
    const float* b    = (const float*)d_in[2];  // (64)
    const float* cent = (const float*)d_in[3];  // (64, 256)
    float* out = (float*)d_out;                 // (128, 16384)

    cudaFuncSetAttribute(netvlad_mma, cudaFuncAttributeMaxDynamicSharedMemorySize, SM_TOTAL);
    netvlad_mma<<<2 * NB, 256, SM_TOTAL>>>(x, w, b, cent, out);
}

// round 13
// speedup vs baseline: 1.3643x; 1.3643x over previous
#include <cuda_runtime.h>
#include <cuda_bf16.h>
#include <cstdint>

#define NB 128
#define CD 256
#define KK 64
#define PT 1024

// ---- smem byte offsets ----
#define SM_X0   0            // x tile bf16 [256 c][136 p] (stride 272 B)
#define SM_X1   69632
#define XSTR    272
#define SM_W    139264       // W bf16 [64 k][264 c]
#define WSTR    528
#define SM_AT0  173056       // at bf16 [64 k][136 p], double buffered
#define SM_AT1  190464
#define ASTR    272
#define SM_SQ0  207872       // 128 x 9 f, double buffered
#define SM_SQ1  212480
#define SM_RED  217088       // 64 x 33 f (asum accum) / 64 x 5 f (epilogue)
#define SM_ASUM 225536
#define SM_RK   225792
#define SM_BIAS 226048
#define SM_G2   226304
#define SM_TOTAL 226312

__device__ __forceinline__ uint32_t smem_u32(const void* p) {
    uint32_t a;
    asm("{ .reg .u64 t; cvta.to.shared.u64 t, %1; cvt.u32.u64 %0, t; }" : "=r"(a) : "l"(p));
    return a;
}
__device__ __forceinline__ uint32_t bf2(float lo, float hi) {
    uint32_t r;
    asm("cvt.rn.bf16x2.f32 %0, %1, %2;" : "=r"(r) : "f"(hi), "f"(lo));
    return r;
}
__device__ __forceinline__ void ldm4t(uint32_t* r, uint32_t addr) {
    asm volatile("ldmatrix.sync.aligned.m8n8.x4.trans.shared.b16 {%0,%1,%2,%3}, [%4];"
                 : "=r"(r[0]), "=r"(r[1]), "=r"(r[2]), "=r"(r[3]) : "r"(addr));
}
__device__ __forceinline__ void ldm4(uint32_t* r, uint32_t addr) {
    asm volatile("ldmatrix.sync.aligned.m8n8.x4.shared.b16 {%0,%1,%2,%3}, [%4];"
                 : "=r"(r[0]), "=r"(r[1]), "=r"(r[2]), "=r"(r[3]) : "r"(addr));
}
__device__ __forceinline__ void mma_bf16(float* d, const uint32_t* a, uint32_t b0, uint32_t b1) {
    asm volatile("mma.sync.aligned.m16n8k16.row.col.f32.bf16.bf16.f32 "
                 "{%0,%1,%2,%3}, {%4,%5,%6,%7}, {%8,%9}, {%0,%1,%2,%3};"
                 : "+f"(d[0]), "+f"(d[1]), "+f"(d[2]), "+f"(d[3])
                 : "r"(a[0]), "r"(a[1]), "r"(a[2]), "r"(a[3]), "r"(b0), "r"(b1));
}
__device__ __forceinline__ void sts16(uint32_t addr, __nv_bfloat16 v) {
    unsigned short u = *(unsigned short*)&v;
    asm volatile("st.shared.u16 [%0], %1;" :: "r"(addr), "h"(u) : "memory");
}

__global__ __launch_bounds__(512, 1) void netvlad_mma(
    const float* __restrict__ x, const float* __restrict__ w,
    const float* __restrict__ b, const float* __restrict__ cent,
    float* __restrict__ out) {
    extern __shared__ char smem[];
    float* smf = (float*)smem;
    const uint32_t sb = smem_u32(smem);
    const int t = threadIdx.x, lane = t & 31, wp = t >> 5;
    const int la = lane & 7, grp = lane >> 3, qr = lane >> 2, qc = lane & 3;
    const int n = blockIdx.x;
    const float* xn = x + (size_t)n * CD * PT;
    const int wq = wp - 8;                   // valid for warps 8-15
    const int kg = wq & 1, cg = wq >> 1;     // GEMM2: k32 x c64 per warp

    // ---- pre-loop: warps 0-7 load W + bias + zero RED; warps 8-15 load tile 0 ----
    if (wp < 8) {
#pragma unroll
        for (int i = 0; i < 32; i++) {
            int id2 = t + (i << 8);
            int kk = id2 >> 7, c2 = id2 & 127;
            float2 v = ((const float2*)w)[id2];
            *(uint32_t*)(smem + SM_W + kk * WSTR + c2 * 4) = bf2(v.x, v.y);
        }
        if (t < KK) smf[(SM_BIAS >> 2) + t] = b[t];
        for (int i = t; i < 64 * 33; i += 256) smf[(SM_RED >> 2) + i] = 0.f;
    } else {
        const float* xp = xn + lane * 4;
        float s0 = 0.f, s1 = 0.f, s2 = 0.f, s3 = 0.f;
#pragma unroll 8
        for (int ci = 0; ci < 32; ci++) {
            int c = wq * 32 + ci;
            float4 v = *(const float4*)(xp + (size_t)c * PT);
            s0 += v.x * v.x; s1 += v.y * v.y; s2 += v.z * v.z; s3 += v.w * v.w;
            *(uint2*)(smem + SM_X0 + c * XSTR + lane * 8) =
                make_uint2(bf2(v.x, v.y), bf2(v.z, v.w));
        }
        float* sq = smf + (SM_SQ0 >> 2);
        sq[(lane * 4 + 0) * 9 + wq] = s0;
        sq[(lane * 4 + 1) * 9 + wq] = s1;
        sq[(lane * 4 + 2) * 9 + wq] = s2;
        sq[(lane * 4 + 3) * 9 + wq] = s3;
    }

    // ldmatrix offsets
    const uint32_t aG1off = (uint32_t)(la + ((grp >> 1) << 3)) * XSTR +
                            (uint32_t)(wp * 16 + ((grp & 1) << 3)) * 2;
    const uint32_t wG1 = sb + SM_W + (uint32_t)la * WSTR + (uint32_t)(grp * 8) * 2;
    const uint32_t aG2off = (uint32_t)(kg * 32 + la + ((grp & 1) << 3)) * ASTR +
                            (uint32_t)((grp >> 1) << 3) * 2;
    const uint32_t xG2off = (uint32_t)(cg * 64 + la) * XSTR + (uint32_t)(grp * 8) * 2;
    const int plo = wp * 16 + qr, phi = plo + 8;

    float agg[2][8][4];
#pragma unroll
    for (int i = 0; i < 2; i++)
#pragma unroll
        for (int j = 0; j < 8; j++)
#pragma unroll
            for (int q = 0; q < 4; q++) agg[i][j][q] = 0.f;

    __syncthreads();

    // ---- 3-stage pipeline: GEMM1(it) || GEMM2(it-1) -> load(it+1) ----
    for (int it = 0; it < 9; it++) {
        if (wp < 8) {
            if (it < 8) {
                const uint32_t aG1 = sb + ((it & 1) ? SM_X1 : SM_X0) + aG1off;
                const uint32_t atw = sb + ((it & 1) ? SM_AT1 : SM_AT0);
                const uint32_t sqb = (it & 1) ? SM_SQ1 : SM_SQ0;

                float acc[8][4];
#pragma unroll
                for (int i = 0; i < 8; i++)
#pragma unroll
                    for (int q = 0; q < 4; q++) acc[i][q] = 0.f;
#pragma unroll
                for (int cb32 = 0; cb32 < 256; cb32 += 32) {
                    uint32_t afA[4], afB[4];
                    ldm4t(afA, aG1 + (uint32_t)cb32 * XSTR);
                    ldm4t(afB, aG1 + (uint32_t)(cb32 + 16) * XSTR);
#pragma unroll
                    for (int nt = 0; nt < 8; nt++) {
                        uint32_t wf[4];
                        ldm4(wf, wG1 + (uint32_t)nt * (8 * WSTR) + (uint32_t)cb32 * 2);
                        mma_bf16(acc[nt], afA, wf[0], wf[1]);
                        mma_bf16(acc[nt], afB, wf[2], wf[3]);
                    }
                }

                // inv-norm (full per-thread sum, broadcast LDS)
                float qlo = 0.f, qhi = 0.f;
                const float* sqp = smf + (sqb >> 2);
#pragma unroll
                for (int i = 0; i < 8; i++) {
                    qlo += sqp[plo * 9 + i];
                    qhi += sqp[phi * 9 + i];
                }
                const float invlo = 1.0f / fmaxf(sqrtf(qlo), 1e-12f);
                const float invhi = 1.0f / fmaxf(sqrtf(qhi), 1e-12f);

                float mlo = -1e30f, mhi = -1e30f;
#pragma unroll
                for (int nt = 0; nt < 8; nt++) {
                    float b0 = smf[(SM_BIAS >> 2) + nt * 8 + qc * 2];
                    float b1 = smf[(SM_BIAS >> 2) + nt * 8 + qc * 2 + 1];
                    acc[nt][0] = acc[nt][0] * invlo + b0;
                    acc[nt][1] = acc[nt][1] * invlo + b1;
                    acc[nt][2] = acc[nt][2] * invhi + b0;
                    acc[nt][3] = acc[nt][3] * invhi + b1;
                    mlo = fmaxf(mlo, fmaxf(acc[nt][0], acc[nt][1]));
                    mhi = fmaxf(mhi, fmaxf(acc[nt][2], acc[nt][3]));
                }
                mlo = fmaxf(mlo, __shfl_xor_sync(0xffffffffu, mlo, 1));
                mlo = fmaxf(mlo, __shfl_xor_sync(0xffffffffu, mlo, 2));
                mhi = fmaxf(mhi, __shfl_xor_sync(0xffffffffu, mhi, 1));
                mhi = fmaxf(mhi, __shfl_xor_sync(0xffffffffu, mhi, 2));
                float slo = 0.f, shi = 0.f;
#pragma unroll
                for (int nt = 0; nt < 8; nt++) {
                    acc[nt][0] = __expf(acc[nt][0] - mlo); slo += acc[nt][0];
                    acc[nt][1] = __expf(acc[nt][1] - mlo); slo += acc[nt][1];
                    acc[nt][2] = __expf(acc[nt][2] - mhi); shi += acc[nt][2];
                    acc[nt][3] = __expf(acc[nt][3] - mhi); shi += acc[nt][3];
                }
                slo += __shfl_xor_sync(0xffffffffu, slo, 1);
                slo += __shfl_xor_sync(0xffffffffu, slo, 2);
                shi += __shfl_xor_sync(0xffffffffu, shi, 1);
                shi += __shfl_xor_sync(0xffffffffu, shi, 2);
                const float rlo = 1.0f / slo, rhi = 1.0f / shi;
                const float wlo = rlo * invlo, whi = rhi * invhi;

                float asv[16];
#pragma unroll
                for (int nt = 0; nt < 8; nt++) {
                    float a0 = acc[nt][0] * rlo, a1 = acc[nt][1] * rlo;
                    float a2 = acc[nt][2] * rhi, a3 = acc[nt][3] * rhi;
                    asv[nt * 2]     = a0 + a2;
                    asv[nt * 2 + 1] = a1 + a3;
                    int k0 = nt * 8 + qc * 2;
                    uint32_t base0 = atw + (uint32_t)k0 * ASTR;
                    sts16(base0 + (uint32_t)plo * 2, __float2bfloat16(acc[nt][0] * wlo));
                    sts16(base0 + ASTR + (uint32_t)plo * 2, __float2bfloat16(acc[nt][1] * wlo));
                    sts16(base0 + (uint32_t)phi * 2, __float2bfloat16(acc[nt][2] * whi));
                    sts16(base0 + ASTR + (uint32_t)phi * 2, __float2bfloat16(acc[nt][3] * whi));
                }
#pragma unroll
                for (int j = 0; j < 16; j++)
                    asv[j] += __shfl_xor_sync(0xffffffffu, asv[j], 4);
                if ((qr & 1) == 0) {
                    int col = wp * 4 + (qr >> 1);
#pragma unroll
                    for (int nt = 0; nt < 8; nt++) {
                        int k0 = nt * 8 + qc * 2;
                        smf[(SM_RED >> 2) + k0 * 33 + col] += asv[nt * 2];
                        smf[(SM_RED >> 2) + (k0 + 1) * 33 + col] += asv[nt * 2 + 1];
                    }
                }
            }
        } else {
            if (it > 0) {
                // GEMM2(it-1): agg[k32][c64] += at @ x^T  (streamed, low reg pressure)
                const uint32_t xg2 = sb + ((it & 1) ? SM_X0 : SM_X1) + xG2off;
                const uint32_t ag2 = sb + ((it & 1) ? SM_AT0 : SM_AT1) + aG2off;
#pragma unroll
                for (int q4 = 0; q4 < 4; q4++) {
                    const uint32_t pb2 = (uint32_t)(q4 * 64);
                    uint32_t afr[2][2][4];
#pragma unroll
                    for (int mt = 0; mt < 2; mt++) {
                        ldm4(afr[mt][0], ag2 + (uint32_t)mt * 16 * ASTR + pb2);
                        ldm4(afr[mt][1], ag2 + (uint32_t)mt * 16 * ASTR + pb2 + 32);
                    }
#pragma unroll
                    for (int nt = 0; nt < 8; nt++) {
                        uint32_t bfr[4];
                        ldm4(bfr, xg2 + (uint32_t)nt * (8 * XSTR) + pb2);
                        mma_bf16(agg[0][nt], afr[0][0], bfr[0], bfr[1]);
                        mma_bf16(agg[0][nt], afr[0][1], bfr[2], bfr[3]);
                        mma_bf16(agg[1][nt], afr[1][0], bfr[0], bfr[1]);
                        mma_bf16(agg[1][nt], afr[1][1], bfr[2], bfr[3]);
                    }
                }
            }
            if (it > 0 && it < 7)
                asm volatile("bar.sync 1, 256;" ::: "memory");  // order GEMM2 reads vs loads
            if (it < 7) {
                // load tile it+1 (tiles 1..7) into the buffer GEMM2 just released
                const uint32_t xnb = (it & 1) ? SM_X0 : SM_X1;
                const uint32_t sqn = (it & 1) ? SM_SQ0 : SM_SQ1;
                const float* xp = xn + ((it + 1) << 7) + lane * 4;
                float s0 = 0.f, s1 = 0.f, s2 = 0.f, s3 = 0.f;
#pragma unroll 8
                for (int ci = 0; ci < 32; ci++) {
                    int c = wq * 32 + ci;
                    float4 v = *(const float4*)(xp + (size_t)c * PT);
                    s0 += v.x * v.x; s1 += v.y * v.y; s2 += v.z * v.z; s3 += v.w * v.w;
                    *(uint2*)(smem + xnb + c * XSTR + lane * 8) =
                        make_uint2(bf2(v.x, v.y), bf2(v.z, v.w));
                }
                float* sq = smf + (sqn >> 2);
                sq[(lane * 4 + 0) * 9 + wq] = s0;
                sq[(lane * 4 + 1) * 9 + wq] = s1;
                sq[(lane * 4 + 2) * 9 + wq] = s2;
                sq[(lane * 4 + 3) * 9 + wq] = s3;
            }
        }
        __syncthreads();
    }

    // ---- epilogue ----
    if (t < 64) {
        float s = 0.f;
#pragma unroll
        for (int i = 0; i < 32; i++) s += smf[(SM_RED >> 2) + t * 33 + i];
        smf[(SM_ASUM >> 2) + t] = s;
    }
    __syncthreads();
    if (wp >= 8) {
#pragma unroll
        for (int mt = 0; mt < 2; mt++) {
            int kA = kg * 32 + mt * 16 + qr, kB = kA + 8;
            float as0 = smf[(SM_ASUM >> 2) + kA];
            float as1 = smf[(SM_ASUM >> 2) + kB];
#pragma unroll
            for (int nt = 0; nt < 8; nt++) {
                int c0 = cg * 64 + nt * 8 + qc * 2;
                float2 ce0 = *(const float2*)(cent + kA * CD + c0);
                float2 ce1 = *(const float2*)(cent + kB * CD + c0);
                agg[mt][nt][0] -= as0 * ce0.x;
                agg[mt][nt][1] -= as0 * ce0.y;
                agg[mt][nt][2] -= as1 * ce1.x;
                agg[mt][nt][3] -= as1 * ce1.y;
            }
        }
#pragma unroll
        for (int mt = 0; mt < 2; mt++) {
            float sA = 0.f, sB = 0.f;
#pragma unroll
            for (int nt = 0; nt < 8; nt++) {
                sA += agg[mt][nt][0] * agg[mt][nt][0] + agg[mt][nt][1] * agg[mt][nt][1];
                sB += agg[mt][nt][2] * agg[mt][nt][2] + agg[mt][nt][3] * agg[mt][nt][3];
            }
            sA += __shfl_xor_sync(0xffffffffu, sA, 1);
            sA += __shfl_xor_sync(0xffffffffu, sA, 2);
            sB += __shfl_xor_sync(0xffffffffu, sB, 1);
            sB += __shfl_xor_sync(0xffffffffu, sB, 2);
            if (qc == 0) {
                int kA = kg * 32 + mt * 16 + qr;
                smf[(SM_RED >> 2) + kA * 5 + cg] = sA;
                smf[(SM_RED >> 2) + (kA + 8) * 5 + cg] = sB;
            }
        }
    }
    __syncthreads();
    if (t < 64) {
        float ss = 0.f;
#pragma unroll
        for (int i = 0; i < 4; i++) ss += smf[(SM_RED >> 2) + t * 5 + i];
        float dk = fmaxf(sqrtf(ss), 1e-12f);
        smf[(SM_RK >> 2) + t] = 1.0f / dk;
        float gp = ss / (dk * dk);
        gp += __shfl_xor_sync(0xffffffffu, gp, 16);
        gp += __shfl_xor_sync(0xffffffffu, gp, 8);
        gp += __shfl_xor_sync(0xffffffffu, gp, 4);
        gp += __shfl_xor_sync(0xffffffffu, gp, 2);
        gp += __shfl_xor_sync(0xffffffffu, gp, 1);
        if (lane == 0) smf[(SM_G2 >> 2) + wp] = gp;
    }
    __syncthreads();
    if (wp >= 8) {
        const float rg = 1.0f / fmaxf(sqrtf(smf[SM_G2 >> 2] + smf[(SM_G2 >> 2) + 1]), 1e-12f);
        float* on = out + (size_t)n * KK * CD;
#pragma unroll
        for (int mt = 0; mt < 2; mt++) {
            int kA = kg * 32 + mt * 16 + qr, kB = kA + 8;
            float r0 = smf[(SM_RK >> 2) + kA] * rg;
            float r1 = smf[(SM_RK >> 2) + kB] * rg;
#pragma unroll
            for (int nt = 0; nt < 8; nt++) {
                int c0 = cg * 64 + nt * 8 + qc * 2;
                *(float2*)(on + kA * CD + c0) =
                    make_float2(agg[mt][nt][0] * r0, agg[mt][nt][1] * r0);
                *(float2*)(on + kB * CD + c0) =
                    make_float2(agg[mt][nt][2] * r1, agg[mt][nt][3] * r1);
            }
        }
    }
}

// ------------------------------------------------------------------------------
extern "C" void kernel_launch(void* const* d_in, const int* in_sizes, int n_in,
                              void* d_out, int out_size) {
    const float* x    = (const float*)d_in[0];  // (128, 256, 32, 32)
    const float* w    = (const float*)d_in[1];  // (64, 256)
    const float* b    = (const float*)d_in[2];  // (64)
    const float* cent = (const float*)d_in[3];  // (64, 256)
    float* out = (float*)d_out;                 // (128, 16384)

    cudaFuncSetAttribute(netvlad_mma, cudaFuncAttributeMaxDynamicSharedMemorySize, SM_TOTAL);
    netvlad_mma<<<NB, 512, SM_TOTAL>>>(x, w, b, cent, out);
}

// round 14
// speedup vs baseline: 1.5000x; 1.0995x over previous
#include <cuda_runtime.h>
#include <cuda_bf16.h>
#include <cstdint>

#define NB 128
#define CD 256
#define KK 64
#define PT 1024

// ---- smem byte offsets ----
#define SM_X0   0            // x tile bf16 [256 c][136 p] (stride 272 B)
#define SM_X1   69632
#define XSTR    272
#define SM_W    139264       // W bf16 [64 k][264 c] (stride 528 B)
#define WSTR    528
#define SM_AT   173056       // at bf16 [64 k][136 p]
#define ASTR    272
#define SM_SQ0  190464       // 128 x 17 f
#define SM_SQ1  199168       // 128 x 17 f
#define SM_RED  207872       // 64 x 33 f (asum accum across tiles) / 64 x 9 f (epilogue)
#define SM_ASUM 216320       // 64 f
#define SM_RK   216576       // 64 f
#define SM_BIAS 216832       // 64 f
#define SM_G2   217088       // 2 f
#define SM_TOTAL 217096

__device__ __forceinline__ uint32_t smem_u32(const void* p) {
    uint32_t a;
    asm("{ .reg .u64 t; cvta.to.shared.u64 t, %1; cvt.u32.u64 %0, t; }" : "=r"(a) : "l"(p));
    return a;
}
__device__ __forceinline__ uint32_t bf2(float lo, float hi) {
    uint32_t r;
    asm("cvt.rn.bf16x2.f32 %0, %1, %2;" : "=r"(r) : "f"(hi), "f"(lo));
    return r;
}
__device__ __forceinline__ void ldm4t(uint32_t* r, uint32_t addr) {
    asm volatile("ldmatrix.sync.aligned.m8n8.x4.trans.shared.b16 {%0,%1,%2,%3}, [%4];"
                 : "=r"(r[0]), "=r"(r[1]), "=r"(r[2]), "=r"(r[3]) : "r"(addr));
}
__device__ __forceinline__ void ldm4(uint32_t* r, uint32_t addr) {
    asm volatile("ldmatrix.sync.aligned.m8n8.x4.shared.b16 {%0,%1,%2,%3}, [%4];"
                 : "=r"(r[0]), "=r"(r[1]), "=r"(r[2]), "=r"(r[3]) : "r"(addr));
}
__device__ __forceinline__ void mma_bf16(float* d, const uint32_t* a, uint32_t b0, uint32_t b1) {
    asm volatile("mma.sync.aligned.m16n8k16.row.col.f32.bf16.bf16.f32 "
                 "{%0,%1,%2,%3}, {%4,%5,%6,%7}, {%8,%9}, {%0,%1,%2,%3};"
                 : "+f"(d[0]), "+f"(d[1]), "+f"(d[2]), "+f"(d[3])
                 : "r"(a[0]), "r"(a[1]), "r"(a[2]), "r"(a[3]), "r"(b0), "r"(b1));
}
__device__ __forceinline__ void sts16(uint32_t addr, __nv_bfloat16 v) {
    unsigned short u = *(unsigned short*)&v;
    asm volatile("st.shared.u16 [%0], %1;" :: "r"(addr), "h"(u) : "memory");
}
__device__ __forceinline__ void pfL2(const void* p) {
    asm volatile("prefetch.global.L2 [%0];" :: "l"(p));
}

__global__ __launch_bounds__(512, 1) void netvlad_mma(
    const float* __restrict__ x, const float* __restrict__ w,
    const float* __restrict__ b, const float* __restrict__ cent,
    float* __restrict__ out) {
    extern __shared__ char smem[];
    float* smf = (float*)smem;
    const uint32_t sb = smem_u32(smem);
    const int t = threadIdx.x, lane = t & 31, wp = t >> 5;
    const int la = lane & 7, grp = lane >> 3, qr = lane >> 2, qc = lane & 3;
    const int kg = wp & 1, cg = wp >> 1;        // GEMM2 tiling (k32 x c32)
    const int n = blockIdx.x;
    const float* xn = x + (size_t)n * CD * PT;
    const int wq = wp - 8;                      // loader index (warps 8-15)

    // ---- one-time: W -> bf16 smem, bias, zero RED ----
#pragma unroll
    for (int i = 0; i < 16; i++) {
        int id2 = t + (i << 9);
        int kk = id2 >> 7, c2 = id2 & 127;
        float2 v = ((const float2*)w)[id2];
        *(uint32_t*)(smem + SM_W + kk * WSTR + c2 * 4) = bf2(v.x, v.y);
    }
    if (t < KK) smf[(SM_BIAS >> 2) + t] = b[t];
    for (int i = t; i < 64 * 33; i += 512) smf[(SM_RED >> 2) + i] = 0.f;

    // ldmatrix offsets
    const uint32_t aG1off = (uint32_t)(la + ((grp >> 1) << 3)) * XSTR +
                            (uint32_t)(wp * 16 + ((grp & 1) << 3)) * 2;
    const uint32_t wG1 = sb + SM_W + (uint32_t)la * WSTR + (uint32_t)(grp * 8) * 2;
    const uint32_t aG2 = sb + SM_AT + (uint32_t)(kg * 32 + la + ((grp & 1) << 3)) * ASTR +
                         (uint32_t)((grp >> 1) << 3) * 2;
    const uint32_t xG2off = (uint32_t)(cg * 32 + la) * XSTR + (uint32_t)(grp * 8) * 2;
    const int plo = wp * 16 + qr, phi = plo + 8;   // GEMM1 pixel rows (warps 0-7)

    float agg[2][4][4];
#pragma unroll
    for (int i = 0; i < 2; i++)
#pragma unroll
        for (int j = 0; j < 4; j++)
#pragma unroll
            for (int q = 0; q < 4; q++) agg[i][j][q] = 0.f;

    // ---- pre-loop: tile 0 -> X0 + SQ0 (all 512 threads, 16 SQ cols) ----
    {
        const int pq = t & 31, cb = t >> 5;   // cb 0..15
        const float* xp = xn + pq * 4;
        float s0 = 0.f, s1 = 0.f, s2 = 0.f, s3 = 0.f;
#pragma unroll
        for (int i = 0; i < 16; i++) {
            int c = cb + (i << 4);
            float4 v = *(const float4*)(xp + (size_t)c * PT);
            s0 += v.x * v.x; s1 += v.y * v.y; s2 += v.z * v.z; s3 += v.w * v.w;
            *(uint2*)(smem + SM_X0 + c * XSTR + pq * 8) =
                make_uint2(bf2(v.x, v.y), bf2(v.z, v.w));
        }
        float* sq = smf + (SM_SQ0 >> 2);
        sq[(pq * 4 + 0) * 17 + cb] = s0;
        sq[(pq * 4 + 1) * 17 + cb] = s1;
        sq[(pq * 4 + 2) * 17 + cb] = s2;
        sq[(pq * 4 + 3) * 17 + cb] = s3;
    }
    __syncthreads();

    for (int tl = 0; tl < 8; tl++) {
        const uint32_t xb  = (tl & 1) ? SM_X1 : SM_X0;
        const uint32_t xnb = (tl & 1) ? SM_X0 : SM_X1;
        const uint32_t sqb = (tl & 1) ? SM_SQ1 : SM_SQ0;
        const uint32_t sqn = (tl & 1) ? SM_SQ0 : SM_SQ1;

        float asv[16];   // asum scalars, computed pre-S1, reduced post-S1 (warps 0-7)

        // ======== half 1: warps 0-7 GEMM1+softmax  |  warps 8-15 load tl+1 ========
        if (wp < 8) {
            const uint32_t aG1 = sb + xb + aG1off;
            float acc[8][4];
#pragma unroll
            for (int i = 0; i < 8; i++)
#pragma unroll
                for (int q = 0; q < 4; q++) acc[i][q] = 0.f;
#pragma unroll
            for (int cb32 = 0; cb32 < 256; cb32 += 32) {
                uint32_t afA[4], afB[4];
                ldm4t(afA, aG1 + (uint32_t)cb32 * XSTR);
                ldm4t(afB, aG1 + (uint32_t)(cb32 + 16) * XSTR);
#pragma unroll
                for (int nt = 0; nt < 8; nt++) {
                    uint32_t wf[4];
                    ldm4(wf, wG1 + (uint32_t)nt * (8 * WSTR) + (uint32_t)cb32 * 2);
                    mma_bf16(acc[nt], afA, wf[0], wf[1]);
                    mma_bf16(acc[nt], afB, wf[2], wf[3]);
                }
            }

            // warp-local softmax over k=64 (qc lanes split k, qr lanes split p)
            float qlo = 0.f, qhi = 0.f;
#pragma unroll
            for (int i = 0; i < 4; i++) {
                qlo += smf[(sqb >> 2) + plo * 17 + qc * 4 + i];
                qhi += smf[(sqb >> 2) + phi * 17 + qc * 4 + i];
            }
            qlo += __shfl_xor_sync(0xffffffffu, qlo, 1);
            qlo += __shfl_xor_sync(0xffffffffu, qlo, 2);
            qhi += __shfl_xor_sync(0xffffffffu, qhi, 1);
            qhi += __shfl_xor_sync(0xffffffffu, qhi, 2);
            const float invlo = 1.0f / fmaxf(sqrtf(qlo), 1e-12f);
            const float invhi = 1.0f / fmaxf(sqrtf(qhi), 1e-12f);

            float mlo = -1e30f, mhi = -1e30f;
#pragma unroll
            for (int nt = 0; nt < 8; nt++) {
                float b0 = smf[(SM_BIAS >> 2) + nt * 8 + qc * 2];
                float b1 = smf[(SM_BIAS >> 2) + nt * 8 + qc * 2 + 1];
                acc[nt][0] = acc[nt][0] * invlo + b0;
                acc[nt][1] = acc[nt][1] * invlo + b1;
                acc[nt][2] = acc[nt][2] * invhi + b0;
                acc[nt][3] = acc[nt][3] * invhi + b1;
                mlo = fmaxf(mlo, fmaxf(acc[nt][0], acc[nt][1]));
                mhi = fmaxf(mhi, fmaxf(acc[nt][2], acc[nt][3]));
            }
            mlo = fmaxf(mlo, __shfl_xor_sync(0xffffffffu, mlo, 1));
            mlo = fmaxf(mlo, __shfl_xor_sync(0xffffffffu, mlo, 2));
            mhi = fmaxf(mhi, __shfl_xor_sync(0xffffffffu, mhi, 1));
            mhi = fmaxf(mhi, __shfl_xor_sync(0xffffffffu, mhi, 2));
            float slo = 0.f, shi = 0.f;
#pragma unroll
            for (int nt = 0; nt < 8; nt++) {
                acc[nt][0] = __expf(acc[nt][0] - mlo); slo += acc[nt][0];
                acc[nt][1] = __expf(acc[nt][1] - mlo); slo += acc[nt][1];
                acc[nt][2] = __expf(acc[nt][2] - mhi); shi += acc[nt][2];
                acc[nt][3] = __expf(acc[nt][3] - mhi); shi += acc[nt][3];
            }
            slo += __shfl_xor_sync(0xffffffffu, slo, 1);
            slo += __shfl_xor_sync(0xffffffffu, slo, 2);
            shi += __shfl_xor_sync(0xffffffffu, shi, 1);
            shi += __shfl_xor_sync(0xffffffffu, shi, 2);
            const float rlo = 1.0f / slo, rhi = 1.0f / shi;
            const float wlo = rlo * invlo, whi = rhi * invhi;

#pragma unroll
            for (int nt = 0; nt < 8; nt++) {
                float a0 = acc[nt][0] * rlo, a1 = acc[nt][1] * rlo;
                float a2 = acc[nt][2] * rhi, a3 = acc[nt][3] * rhi;
                asv[nt * 2]     = a0 + a2;
                asv[nt * 2 + 1] = a1 + a3;
                int k0 = nt * 8 + qc * 2;
                uint32_t base0 = sb + SM_AT + (uint32_t)k0 * ASTR;
                sts16(base0 + (uint32_t)plo * 2, __float2bfloat16(acc[nt][0] * wlo));
                sts16(base0 + ASTR + (uint32_t)plo * 2, __float2bfloat16(acc[nt][1] * wlo));
                sts16(base0 + (uint32_t)phi * 2, __float2bfloat16(acc[nt][2] * whi));
                sts16(base0 + ASTR + (uint32_t)phi * 2, __float2bfloat16(acc[nt][3] * whi));
            }
            // (asv reduction deferred to half 2 — off the S1 critical path)
        } else if (tl < 7) {
            // loader warps: x(tl+1) -> other buffer, SQ partials (cols cb & cb+8)
            const int tid2 = t - 256;
            const int pq = tid2 & 31, cb = tid2 >> 5;   // cb 0..7
            const float* xp = xn + (tl * 128 + 128) + pq * 4;
            float sA0 = 0.f, sA1 = 0.f, sA2 = 0.f, sA3 = 0.f;
            float sB0 = 0.f, sB1 = 0.f, sB2 = 0.f, sB3 = 0.f;
#pragma unroll
            for (int i = 0; i < 16; i++) {
                int c = cb + (i << 3);
                float4 v = *(const float4*)(xp + (size_t)c * PT);
                sA0 += v.x * v.x; sA1 += v.y * v.y; sA2 += v.z * v.z; sA3 += v.w * v.w;
                *(uint2*)(smem + xnb + c * XSTR + pq * 8) =
                    make_uint2(bf2(v.x, v.y), bf2(v.z, v.w));
            }
#pragma unroll
            for (int i = 16; i < 32; i++) {
                int c = cb + (i << 3);
                float4 v = *(const float4*)(xp + (size_t)c * PT);
                sB0 += v.x * v.x; sB1 += v.y * v.y; sB2 += v.z * v.z; sB3 += v.w * v.w;
                *(uint2*)(smem + xnb + c * XSTR + pq * 8) =
                    make_uint2(bf2(v.x, v.y), bf2(v.z, v.w));
            }
            float* sq = smf + (sqn >> 2);
            sq[(pq * 4 + 0) * 17 + cb] = sA0;
            sq[(pq * 4 + 1) * 17 + cb] = sA1;
            sq[(pq * 4 + 2) * 17 + cb] = sA2;
            sq[(pq * 4 + 3) * 17 + cb] = sA3;
            sq[(pq * 4 + 0) * 17 + cb + 8] = sB0;
            sq[(pq * 4 + 1) * 17 + cb + 8] = sB1;
            sq[(pq * 4 + 2) * 17 + cb + 8] = sB2;
            sq[(pq * 4 + 3) * 17 + cb + 8] = sB3;
            if (tl == 0) {                       // warm cent into L2 for epilogue
                const float* cp = cent + tid2 * 64;
                pfL2(cp); pfL2(cp + 32);
            }
        }
        __syncthreads();   // S1

        // ======== half 2: deferred asum reduction (warps 0-7) + GEMM2 (all) ========
        if (wp < 8) {
#pragma unroll
            for (int j = 0; j < 16; j++)
                asv[j] += __shfl_xor_sync(0xffffffffu, asv[j], 4);
            if ((qr & 1) == 0) {
                int col = wp * 4 + (qr >> 1);
#pragma unroll
                for (int nt = 0; nt < 8; nt++) {
                    int k0 = nt * 8 + qc * 2;
                    smf[(SM_RED >> 2) + k0 * 33 + col] += asv[nt * 2];
                    smf[(SM_RED >> 2) + (k0 + 1) * 33 + col] += asv[nt * 2 + 1];
                }
            }
        }
        {
            const uint32_t xg2 = sb + xb + xG2off;
#pragma unroll
            for (int q4 = 0; q4 < 4; q4++) {
                const uint32_t pb2 = (uint32_t)(q4 * 32) * 2;
                uint32_t bfr[4][4];
#pragma unroll
                for (int nt = 0; nt < 4; nt++)
                    ldm4(bfr[nt], xg2 + (uint32_t)nt * (8 * XSTR) + pb2);
                uint32_t afr[2][2][4];
#pragma unroll
                for (int mt = 0; mt < 2; mt++) {
                    ldm4(afr[mt][0], aG2 + (uint32_t)mt * 16 * ASTR + pb2);
                    ldm4(afr[mt][1], aG2 + (uint32_t)mt * 16 * ASTR + pb2 + 32);
                }
#pragma unroll
                for (int mt = 0; mt < 2; mt++)
#pragma unroll
                    for (int nt = 0; nt < 4; nt++) {
                        mma_bf16(agg[mt][nt], afr[mt][0], bfr[nt][0], bfr[nt][1]);
                        mma_bf16(agg[mt][nt], afr[mt][1], bfr[nt][2], bfr[nt][3]);
                    }
            }
        }
        __syncthreads();   // S2
    }

    // ---- epilogue: asum fold, vlad = agg - asum*cent, norms, store ----
    if (t < 64) {
        float s = 0.f;
#pragma unroll
        for (int i = 0; i < 32; i++) s += smf[(SM_RED >> 2) + t * 33 + i];
        smf[(SM_ASUM >> 2) + t] = s;
    }
    __syncthreads();
#pragma unroll
    for (int mt = 0; mt < 2; mt++) {
        int kA = kg * 32 + mt * 16 + qr, kB = kA + 8;
        float as0 = smf[(SM_ASUM >> 2) + kA];
        float as1 = smf[(SM_ASUM >> 2) + kB];
#pragma unroll
        for (int nt = 0; nt < 4; nt++) {
            int c0 = cg * 32 + nt * 8 + qc * 2;
            float2 ce0 = *(const float2*)(cent + kA * CD + c0);
            float2 ce1 = *(const float2*)(cent + kB * CD + c0);
            agg[mt][nt][0] -= as0 * ce0.x;
            agg[mt][nt][1] -= as0 * ce0.y;
            agg[mt][nt][2] -= as1 * ce1.x;
            agg[mt][nt][3] -= as1 * ce1.y;
        }
    }
#pragma unroll
    for (int mt = 0; mt < 2; mt++) {
        float sA = 0.f, sB = 0.f;
#pragma unroll
        for (int nt = 0; nt < 4; nt++) {
            sA += agg[mt][nt][0] * agg[mt][nt][0] + agg[mt][nt][1] * agg[mt][nt][1];
            sB += agg[mt][nt][2] * agg[mt][nt][2] + agg[mt][nt][3] * agg[mt][nt][3];
        }
        sA += __shfl_xor_sync(0xffffffffu, sA, 1);
        sA += __shfl_xor_sync(0xffffffffu, sA, 2);
        sB += __shfl_xor_sync(0xffffffffu, sB, 1);
        sB += __shfl_xor_sync(0xffffffffu, sB, 2);
        if (qc == 0) {
            int kA = kg * 32 + mt * 16 + qr;
            smf[(SM_RED >> 2) + kA * 9 + cg] = sA;
            smf[(SM_RED >> 2) + (kA + 8) * 9 + cg] = sB;
        }
    }
    __syncthreads();
    if (t < 64) {
        float ss = 0.f;
#pragma unroll
        for (int i = 0; i < 8; i++) ss += smf[(SM_RED >> 2) + t * 9 + i];
        float dk = fmaxf(sqrtf(ss), 1e-12f);
        smf[(SM_RK >> 2) + t] = 1.0f / dk;
        float gp = ss / (dk * dk);
        gp += __shfl_xor_sync(0xffffffffu, gp, 16);
        gp += __shfl_xor_sync(0xffffffffu, gp, 8);
        gp += __shfl_xor_sync(0xffffffffu, gp, 4);
        gp += __shfl_xor_sync(0xffffffffu, gp, 2);
        gp += __shfl_xor_sync(0xffffffffu, gp, 1);
        if (lane == 0) smf[(SM_G2 >> 2) + wp] = gp;
    }
    __syncthreads();
    const float rg = 1.0f / fmaxf(sqrtf(smf[SM_G2 >> 2] + smf[(SM_G2 >> 2) + 1]), 1e-12f);
    float* on = out + (size_t)n * KK * CD;
#pragma unroll
    for (int mt = 0; mt < 2; mt++) {
        int kA = kg * 32 + mt * 16 + qr, kB = kA + 8;
        float r0 = smf[(SM_RK >> 2) + kA] * rg;
        float r1 = smf[(SM_RK >> 2) + kB] * rg;
#pragma unroll
        for (int nt = 0; nt < 4; nt++) {
            int c0 = cg * 32 + nt * 8 + qc * 2;
            *(float2*)(on + kA * CD + c0) =
                make_float2(agg[mt][nt][0] * r0, agg[mt][nt][1] * r0);
            *(float2*)(on + kB * CD + c0) =
                make_float2(agg[mt][nt][2] * r1, agg[mt][nt][3] * r1);
        }
    }
}

// ------------------------------------------------------------------------------
extern "C" void kernel_launch(void* const* d_in, const int* in_sizes, int n_in,
                              void* d_out, int out_size) {
    const float* x    = (const float*)d_in[0];  // (128, 256, 32, 32)
    const float* w    = (const float*)d_in[1];  // (64, 256)
    const float* b    = (const float*)d_in[2];  // (64)
    const float* cent = (const float*)d_in[3];  // (64, 256)
    float* out = (float*)d_out;                 // (128, 16384)

    cudaFuncSetAttribute(netvlad_mma, cudaFuncAttributeMaxDynamicSharedMemorySize, SM_TOTAL);
    netvlad_mma<<<NB, 512, SM_TOTAL>>>(x, w, b, cent, out);
}